// round 2
// baseline (speedup 1.0000x reference)
#include <cuda_runtime.h>
#include <cuda_bf16.h>
#include <cstdint>

// Problem constants (fixed by the reference setup)
#define N_NODES_MAX 50000
#define IN_F  256
#define OUT_F 128

// -------- device scratch (no allocation allowed in kernel_launch) --------
// __align__(16): these are read/written with 128-bit accesses.
__device__ __align__(16) float g_m[N_NODES_MAX * OUT_F];  // mean * att * norm1[src]
__device__ __align__(16) float g_v[N_NODES_MAX * OUT_F];  // var * att^2 * norm1[src]^2
__device__ float g_deg[N_NODES_MAX];
__device__ float g_norm1[N_NODES_MAX];

// ---------------------------------------------------------------------
// Kernel 1: zero degree array AND output buffer in one launch.
// out has out_elems floats (poisoned by harness); g_deg has n_nodes floats.
__global__ void zero_all_kernel(float* __restrict__ out, int out_elems, int n_nodes) {
    int i = blockIdx.x * blockDim.x + threadIdx.x;
    if (i < out_elems) out[i] = 0.0f;
    if (i < n_nodes)  g_deg[i] = 0.0f;
}

// Kernel 2: count in-degrees (one thread per edge)
__global__ void deg_count_kernel(const int* __restrict__ edge_dst, int n_edges) {
    int e = blockIdx.x * blockDim.x + threadIdx.x;
    if (e < n_edges) {
        atomicAdd(&g_deg[edge_dst[e]], 1.0f);   // no return use -> REDG
    }
}

// Kernel 3: norm1 = (max(deg,1))^-0.5
__global__ void norm_kernel(int n_nodes) {
    int i = blockIdx.x * blockDim.x + threadIdx.x;
    if (i < n_nodes) {
        float d = fmaxf(g_deg[i], 1.0f);
        g_norm1[i] = rsqrtf(d);
    }
}

// ---------------------------------------------------------------------
// Kernel 4: fused dual GEMM + relu + attention + src-norm scaling.
// Block: 128 threads (one per output column). Tile: TM=16 nodes per block.
// feat tile lives in smem; W columns are streamed from L2 (hot: 2x128KB).
#define TM 16
__global__ __launch_bounds__(OUT_F)
void gemm_fused_kernel(const float* __restrict__ feat,
                       const float* __restrict__ Wm,
                       const float* __restrict__ Wv,
                       int n_nodes) {
    __shared__ float fs[TM][IN_F];   // 16 KB

    const int j = threadIdx.x;            // output column 0..127
    const int node0 = blockIdx.x * TM;

    // cooperative load of the feat tile (coalesced: 128 threads stride the row)
    for (int idx = threadIdx.x; idx < TM * IN_F; idx += OUT_F) {
        int r = idx >> 8;        // /IN_F
        int c = idx & (IN_F - 1);
        int node = node0 + r;
        fs[r][c] = (node < n_nodes) ? feat[node * IN_F + c] : 0.0f;
    }
    __syncthreads();

    float am[TM], av[TM];
#pragma unroll
    for (int i = 0; i < TM; i++) { am[i] = 0.0f; av[i] = 0.0f; }

#pragma unroll 4
    for (int k = 0; k < IN_F; k++) {
        float wm = Wm[k * OUT_F + j];   // coalesced 512B per warp
        float wv = Wv[k * OUT_F + j];
#pragma unroll
        for (int i = 0; i < TM; i++) {
            float f = fs[i][k];         // smem broadcast
            am[i] = fmaf(f, wm, am[i]);
            av[i] = fmaf(f, wv, av[i]);
        }
    }

#pragma unroll
    for (int i = 0; i < TM; i++) {
        int node = node0 + i;
        if (node >= n_nodes) break;
        float mean = fmaxf(am[i], 0.0f);
        float var  = fmaxf(av[i], 0.0f);
        float att  = __expf(-var);          // GAMMA = 1
        float n1   = g_norm1[node];
        float n2   = n1 * n1;
        g_m[node * OUT_F + j] = mean * att * n1;
        g_v[node * OUT_F + j] = var * att * att * n2;
    }
}

// ---------------------------------------------------------------------
// Kernel 5: edge scatter. One warp per edge; each lane handles a float4
// (32 lanes x 16B = 512B = one 128-float row). Vector RED atomics (sm_90+),
// dst-side norm folded in per edge (linear, so exact).
__global__ __launch_bounds__(256)
void edge_scatter_kernel(const int* __restrict__ edge_src,
                         const int* __restrict__ edge_dst,
                         float* __restrict__ out_mean,
                         float* __restrict__ out_var,
                         int n_edges) {
    int gwid = (blockIdx.x * blockDim.x + threadIdx.x) >> 5;
    int lane = threadIdx.x & 31;
    if (gwid >= n_edges) return;

    int s = edge_src[gwid];
    int d = edge_dst[gwid];
    float n1 = g_norm1[d];
    float n2 = n1 * n1;

    const float4* mrow = reinterpret_cast<const float4*>(g_m) + (size_t)s * (OUT_F / 4);
    const float4* vrow = reinterpret_cast<const float4*>(g_v) + (size_t)s * (OUT_F / 4);
    float4 m = mrow[lane];
    float4 v = vrow[lane];

    m.x *= n1; m.y *= n1; m.z *= n1; m.w *= n1;
    v.x *= n2; v.y *= n2; v.z *= n2; v.w *= n2;

    float* mp = out_mean + (size_t)d * OUT_F + lane * 4;
    float* vp = out_var  + (size_t)d * OUT_F + lane * 4;

    asm volatile("red.global.add.v4.f32 [%0], {%1,%2,%3,%4};"
                 :: "l"(mp), "f"(m.x), "f"(m.y), "f"(m.z), "f"(m.w) : "memory");
    asm volatile("red.global.add.v4.f32 [%0], {%1,%2,%3,%4};"
                 :: "l"(vp), "f"(v.x), "f"(v.y), "f"(v.z), "f"(v.w) : "memory");
}

// ---------------------------------------------------------------------
extern "C" void kernel_launch(void* const* d_in, const int* in_sizes, int n_in,
                              void* d_out, int out_size) {
    const float* feat     = (const float*)d_in[0];
    const int*   edge_src = (const int*)  d_in[1];
    const int*   edge_dst = (const int*)  d_in[2];
    const float* Wm       = (const float*)d_in[3];
    const float* Wv       = (const float*)d_in[4];

    const int n_nodes = in_sizes[0] / IN_F;
    const int n_edges = in_sizes[1];

    float* out_mean = (float*)d_out;
    float* out_var  = out_mean + (size_t)n_nodes * OUT_F;

    // 1) zero degree array + output buffer
    int out_elems = n_nodes * OUT_F * 2;
    zero_all_kernel<<<(out_elems + 511) / 512, 512>>>(out_mean, out_elems, n_nodes);

    // 2) degrees + norms
    deg_count_kernel<<<(n_edges + 255) / 256, 256>>>(edge_dst, n_edges);
    norm_kernel<<<(n_nodes + 255) / 256, 256>>>(n_nodes);

    // 3) fused dual GEMM + epilogue
    int n_blocks = (n_nodes + TM - 1) / TM;
    gemm_fused_kernel<<<n_blocks, OUT_F>>>(feat, Wm, Wv, n_nodes);

    // 4) edge scatter (one warp per edge)
    long long total_threads = (long long)n_edges * 32;
    int tpb = 256;
    long long blocks = (total_threads + tpb - 1) / tpb;
    edge_scatter_kernel<<<(unsigned)blocks, tpb>>>(edge_src, edge_dst,
                                                   out_mean, out_var, n_edges);
}

// round 3
// speedup vs baseline: 1.3566x; 1.3566x over previous
#include <cuda_runtime.h>
#include <cuda_fp16.h>
#include <cuda_bf16.h>
#include <cstdint>

#define N_NODES_MAX 50000
#define N_EDGES_MAX 800000
#define IN_F  256
#define OUT_F 128

// -------- device scratch --------
__device__ __align__(16) __half g_mh[N_NODES_MAX * OUT_F];  // fp16 messages: mean*att*norm1[src]
__device__ __align__(16) __half g_vh[N_NODES_MAX * OUT_F];  // fp16 messages: var*att^2*norm1^2[src]
__device__ float g_norm1[N_NODES_MAX];
__device__ int   g_cnt[N_NODES_MAX];          // in-degree counts
__device__ int   g_rp[N_NODES_MAX + 1];       // CSR row pointers (by dst)
__device__ int   g_cur[N_NODES_MAX];          // fill cursors
__device__ int   g_csrc[N_EDGES_MAX];         // CSR src indices
__device__ int   g_bsum[128];                 // scan block sums

// ---------------------------------------------------------------------
__global__ void zero_cnt_kernel(int n) {
    int i = blockIdx.x * blockDim.x + threadIdx.x;
    if (i < n) g_cnt[i] = 0;
}

__global__ void count_kernel(const int* __restrict__ edge_dst, int n_edges) {
    int e = blockIdx.x * blockDim.x + threadIdx.x;
    if (e < n_edges) atomicAdd(&g_cnt[edge_dst[e]], 1);
}

// ----- 3-phase exclusive scan of g_cnt into g_rp (rp[0]=0, rp[i+1]=incl) ----
#define SCAN_B 512
__global__ void scan1_kernel(int n) {
    __shared__ int sh[SCAN_B];
    int i = blockIdx.x * SCAN_B + threadIdx.x;
    int v = (i < n) ? g_cnt[i] : 0;
    sh[threadIdx.x] = v;
    __syncthreads();
    for (int off = 1; off < SCAN_B; off <<= 1) {
        int t = (threadIdx.x >= off) ? sh[threadIdx.x - off] : 0;
        __syncthreads();
        sh[threadIdx.x] += t;
        __syncthreads();
    }
    if (i < n) g_rp[i + 1] = sh[threadIdx.x];
    if (threadIdx.x == SCAN_B - 1) g_bsum[blockIdx.x] = sh[threadIdx.x];
    if (i == 0) g_rp[0] = 0;
}

__global__ void scan2_kernel(int nb) {   // one block of 128 threads, nb <= 128
    __shared__ int sh[128];
    int v = (threadIdx.x < nb) ? g_bsum[threadIdx.x] : 0;
    sh[threadIdx.x] = v;
    __syncthreads();
    for (int off = 1; off < 128; off <<= 1) {
        int t = (threadIdx.x >= off) ? sh[threadIdx.x - off] : 0;
        __syncthreads();
        sh[threadIdx.x] += t;
        __syncthreads();
    }
    if (threadIdx.x < nb) g_bsum[threadIdx.x] = sh[threadIdx.x];
}

__global__ void scan3_kernel(int n) {
    int i = blockIdx.x * SCAN_B + threadIdx.x;
    if (i < n) {
        int add = (blockIdx.x > 0) ? g_bsum[blockIdx.x - 1] : 0;
        int rp = g_rp[i + 1] + add;
        g_rp[i + 1] = rp;
        g_cur[i] = rp - g_cnt[i];   // exclusive start = fill cursor
    }
}

__global__ void norm_kernel(int n) {
    int i = blockIdx.x * blockDim.x + threadIdx.x;
    if (i < n) {
        float d = fmaxf((float)g_cnt[i], 1.0f);
        g_norm1[i] = rsqrtf(d);
    }
}

__global__ void fill_kernel(const int* __restrict__ edge_src,
                            const int* __restrict__ edge_dst, int n_edges) {
    int e = blockIdx.x * blockDim.x + threadIdx.x;
    if (e < n_edges) {
        int d = edge_dst[e];
        int pos = atomicAdd(&g_cur[d], 1);
        g_csrc[pos] = edge_src[e];
    }
}

// ---------------------------------------------------------------------
// Dual SGEMM, 2D register tiling. Block 256 thr, tile BM=64 x (128 cols x 2 mats).
// Thread computes 8 rows x 4 cols x 2 matrices. KC=16 k-chunk.
#define BM 64
#define KC 16
__global__ __launch_bounds__(256, 2)
void gemm_fused_kernel(const float* __restrict__ feat,
                       const float* __restrict__ Wm,
                       const float* __restrict__ Wv,
                       int n_nodes) {
    __shared__ __align__(16) float As[KC][BM];       // 4 KB (transposed feat tile)
    __shared__ __align__(16) float Wms[KC][OUT_F];   // 8 KB
    __shared__ __align__(16) float Wvs[KC][OUT_F];   // 8 KB

    const int tid = threadIdx.x;
    const int tx = tid & 31;          // col group: cols tx*4 .. tx*4+3
    const int ty = tid >> 5;          // row group: rows ty*8 .. ty*8+7
    const int node0 = blockIdx.x * BM;
    const int col = tx * 4;

    float am[8][4], av[8][4];
#pragma unroll
    for (int r = 0; r < 8; r++)
#pragma unroll
        for (int c = 0; c < 4; c++) { am[r][c] = 0.0f; av[r][c] = 0.0f; }

    for (int k0 = 0; k0 < IN_F; k0 += KC) {
        // load A tile: 64 rows x 16 k = 256 float4; one per thread.
        {
            int r  = tid >> 2;        // 0..63
            int kq = tid & 3;         // 0..3 -> k offsets kq*4..kq*4+3
            int node = node0 + r;
            float4 a4 = make_float4(0.f, 0.f, 0.f, 0.f);
            if (node < n_nodes)
                a4 = *reinterpret_cast<const float4*>(&feat[(size_t)node * IN_F + k0 + kq * 4]);
            As[kq * 4 + 0][r] = a4.x;
            As[kq * 4 + 1][r] = a4.y;
            As[kq * 4 + 2][r] = a4.z;
            As[kq * 4 + 3][r] = a4.w;
        }
        // load W tiles: 2 x 16 x 128 = 1024 float4; four per thread.
#pragma unroll
        for (int i = 0; i < 4; i++) {
            int flat4 = tid + 256 * i;       // 0..1023
            int mat = flat4 >> 9;            // 0 = mean, 1 = var
            int rem = flat4 & 511;
            int k  = rem >> 5;               // 0..15
            int c4 = rem & 31;               // 0..31
            const float* W = mat ? Wv : Wm;
            float4 w4 = *reinterpret_cast<const float4*>(&W[(size_t)(k0 + k) * OUT_F + c4 * 4]);
            if (mat) *reinterpret_cast<float4*>(&Wvs[k][c4 * 4]) = w4;
            else     *reinterpret_cast<float4*>(&Wms[k][c4 * 4]) = w4;
        }
        __syncthreads();

#pragma unroll
        for (int kk = 0; kk < KC; kk++) {
            float4 a0 = *reinterpret_cast<const float4*>(&As[kk][ty * 8]);
            float4 a1 = *reinterpret_cast<const float4*>(&As[kk][ty * 8 + 4]);
            float4 wm = *reinterpret_cast<const float4*>(&Wms[kk][col]);
            float4 wv = *reinterpret_cast<const float4*>(&Wvs[kk][col]);
            float a[8] = {a0.x, a0.y, a0.z, a0.w, a1.x, a1.y, a1.z, a1.w};
            float wmv[4] = {wm.x, wm.y, wm.z, wm.w};
            float wvv[4] = {wv.x, wv.y, wv.z, wv.w};
#pragma unroll
            for (int r = 0; r < 8; r++) {
#pragma unroll
                for (int c = 0; c < 4; c++) {
                    am[r][c] = fmaf(a[r], wmv[c], am[r][c]);
                    av[r][c] = fmaf(a[r], wvv[c], av[r][c]);
                }
            }
        }
        __syncthreads();
    }

    // epilogue: relu, att = exp(-var), src-norm scaling, fp16 store
#pragma unroll
    for (int r = 0; r < 8; r++) {
        int node = node0 + ty * 8 + r;
        if (node >= n_nodes) break;
        float n1 = g_norm1[node];
        float n2 = n1 * n1;
        float mv[4], vv[4];
#pragma unroll
        for (int c = 0; c < 4; c++) {
            float mean = fmaxf(am[r][c], 0.0f);
            float var  = fmaxf(av[r][c], 0.0f);
            float att  = __expf(-var);
            mv[c] = mean * att * n1;
            vv[c] = var * att * att * n2;
        }
        size_t base = (size_t)node * OUT_F + col;
        *reinterpret_cast<__half2*>(&g_mh[base])     = __floats2half2_rn(mv[0], mv[1]);
        *reinterpret_cast<__half2*>(&g_mh[base + 2]) = __floats2half2_rn(mv[2], mv[3]);
        *reinterpret_cast<__half2*>(&g_vh[base])     = __floats2half2_rn(vv[0], vv[1]);
        *reinterpret_cast<__half2*>(&g_vh[base + 2]) = __floats2half2_rn(vv[2], vv[3]);
    }
}

// ---------------------------------------------------------------------
// Gather reduction: one block per dst node. Threads 0-63: mean half2 cols,
// threads 64-127: var half2 cols. fp32 accumulation, atomic-free output.
__global__ __launch_bounds__(128)
void gather_kernel(float* __restrict__ out_mean,
                   float* __restrict__ out_var) {
    const int d = blockIdx.x;
    const int tid = threadIdx.x;
    const bool is_var = tid >= 64;
    const int c = tid & 63;   // half2 column index (cols 2c, 2c+1)

    const int start = g_rp[d];
    const int end   = g_rp[d + 1];

    __shared__ int sh_src[128];
    const __half2* base = is_var ? reinterpret_cast<const __half2*>(g_vh)
                                 : reinterpret_cast<const __half2*>(g_mh);
    float2 acc = make_float2(0.0f, 0.0f);

    for (int e0 = start; e0 < end; e0 += 128) {
        int cnt = min(128, end - e0);
        if (tid < cnt) sh_src[tid] = g_csrc[e0 + tid];
        __syncthreads();
        for (int i = 0; i < cnt; i++) {
            int s = sh_src[i];
            float2 f = __half22float2(base[(size_t)s * (OUT_F / 2) + c]);
            acc.x += f.x;
            acc.y += f.y;
        }
        __syncthreads();
    }

    float n1 = g_norm1[d];
    float scale = is_var ? n1 * n1 : n1;
    float* outp = is_var ? out_var : out_mean;
    float2 res = make_float2(acc.x * scale, acc.y * scale);
    *reinterpret_cast<float2*>(&outp[(size_t)d * OUT_F + c * 2]) = res;
}

// ---------------------------------------------------------------------
extern "C" void kernel_launch(void* const* d_in, const int* in_sizes, int n_in,
                              void* d_out, int out_size) {
    const float* feat     = (const float*)d_in[0];
    const int*   edge_src = (const int*)  d_in[1];
    const int*   edge_dst = (const int*)  d_in[2];
    const float* Wm       = (const float*)d_in[3];
    const float* Wv       = (const float*)d_in[4];

    const int n_nodes = in_sizes[0] / IN_F;
    const int n_edges = in_sizes[1];

    float* out_mean = (float*)d_out;
    float* out_var  = out_mean + (size_t)n_nodes * OUT_F;

    int nb_scan = (n_nodes + SCAN_B - 1) / SCAN_B;

    // degree histogram -> CSR row ptrs + cursors + norms
    zero_cnt_kernel<<<(n_nodes + 255) / 256, 256>>>(n_nodes);
    count_kernel<<<(n_edges + 255) / 256, 256>>>(edge_dst, n_edges);
    scan1_kernel<<<nb_scan, SCAN_B>>>(n_nodes);
    scan2_kernel<<<1, 128>>>(nb_scan);
    scan3_kernel<<<nb_scan, SCAN_B>>>(n_nodes);
    norm_kernel<<<(n_nodes + 255) / 256, 256>>>(n_nodes);

    // bucket edges by dst
    fill_kernel<<<(n_edges + 255) / 256, 256>>>(edge_src, edge_dst, n_edges);

    // fused dual GEMM + epilogue -> fp16 messages
    gemm_fused_kernel<<<(n_nodes + BM - 1) / BM, 256>>>(feat, Wm, Wv, n_nodes);

    // atomic-free gather reduction
    gather_kernel<<<n_nodes, 128>>>(out_mean, out_var);
}

// round 4
// speedup vs baseline: 2.3026x; 1.6974x over previous
#include <cuda_runtime.h>
#include <cuda_fp16.h>
#include <cuda_bf16.h>
#include <mma.h>
#include <cstdint>

using namespace nvcuda;

#define N_NODES_MAX 50000
#define N_EDGES_MAX 800000
#define IN_F  256
#define OUT_F 128

// -------- device scratch --------
__device__ __align__(16) __half g_mh[N_NODES_MAX * OUT_F];  // relu(mean)*exp(-var)
__device__ __align__(16) __half g_vh[N_NODES_MAX * OUT_F];  // relu(var)*exp(-2var)
__device__ float g_norm1[N_NODES_MAX];
__device__ int   g_cnt[N_NODES_MAX];
__device__ int   g_rp[N_NODES_MAX + 1];
__device__ int   g_cur[N_NODES_MAX];
__device__ int   g_csrc[N_EDGES_MAX];
__device__ int   g_bsum[128];

// ---------------------------------------------------------------------
__global__ void zero_cnt_kernel(int n) {
    int i = blockIdx.x * blockDim.x + threadIdx.x;
    if (i < n) g_cnt[i] = 0;
}

__global__ void count_kernel(const int* __restrict__ edge_dst, int n_edges) {
    int e = blockIdx.x * blockDim.x + threadIdx.x;
    if (e < n_edges) atomicAdd(&g_cnt[edge_dst[e]], 1);
}

#define SCAN_B 512
__global__ void scan1_kernel(int n) {
    __shared__ int sh[SCAN_B];
    int i = blockIdx.x * SCAN_B + threadIdx.x;
    int v = (i < n) ? g_cnt[i] : 0;
    sh[threadIdx.x] = v;
    __syncthreads();
    for (int off = 1; off < SCAN_B; off <<= 1) {
        int t = (threadIdx.x >= off) ? sh[threadIdx.x - off] : 0;
        __syncthreads();
        sh[threadIdx.x] += t;
        __syncthreads();
    }
    if (i < n) g_rp[i + 1] = sh[threadIdx.x];
    if (threadIdx.x == SCAN_B - 1) g_bsum[blockIdx.x] = sh[threadIdx.x];
    if (i == 0) g_rp[0] = 0;
}

__global__ void scan2_kernel(int nb) {
    __shared__ int sh[128];
    int v = (threadIdx.x < nb) ? g_bsum[threadIdx.x] : 0;
    sh[threadIdx.x] = v;
    __syncthreads();
    for (int off = 1; off < 128; off <<= 1) {
        int t = (threadIdx.x >= off) ? sh[threadIdx.x - off] : 0;
        __syncthreads();
        sh[threadIdx.x] += t;
        __syncthreads();
    }
    if (threadIdx.x < nb) g_bsum[threadIdx.x] = sh[threadIdx.x];
}

// scan3 + norm fused
__global__ void scan3_kernel(int n) {
    int i = blockIdx.x * SCAN_B + threadIdx.x;
    if (i < n) {
        int add = (blockIdx.x > 0) ? g_bsum[blockIdx.x - 1] : 0;
        int rp = g_rp[i + 1] + add;
        g_rp[i + 1] = rp;
        int cnt = g_cnt[i];
        g_cur[i] = rp - cnt;
        g_norm1[i] = rsqrtf(fmaxf((float)cnt, 1.0f));
    }
}

__global__ void fill_kernel(const int* __restrict__ edge_src,
                            const int* __restrict__ edge_dst, int n_edges) {
    int e = blockIdx.x * blockDim.x + threadIdx.x;
    if (e < n_edges) {
        int d = edge_dst[e];
        int pos = atomicAdd(&g_cur[d], 1);
        g_csrc[pos] = edge_src[e];
    }
}

// ---------------------------------------------------------------------
// Tensor-core dual GEMM (fp16 in, fp32 acc) + elementwise epilogue.
// Block = 256 threads (8 warps). Tile BM=128 rows, full 128 cols, both W.
// Warp w owns rows [node0 + w*16, +16) for BOTH matrices (epilogue couples them).
#define GBM 128
#define GKC 32
#define AS_LD (GKC + 8)     // 40 halves: conflict-free ldmatrix
#define WS_LD (OUT_F + 8)   // 136 halves

__global__ __launch_bounds__(256, 1)
void gemm_tc_kernel(const float* __restrict__ feat,
                    const float* __restrict__ Wm,
                    const float* __restrict__ Wv,
                    int n_nodes) {
    __shared__ __align__(32) __half As[GBM][AS_LD];      // 10 KB
    __shared__ __align__(32) __half Wms[GKC][WS_LD];     // 8.5 KB
    __shared__ __align__(32) __half Wvs[GKC][WS_LD];     // 8.5 KB
    __shared__ __align__(32) float  stage[8][256];       // 8 KB (16x16 per warp)

    const int tid  = threadIdx.x;
    const int w    = tid >> 5;      // warp id 0..7 -> row strip
    const int lane = tid & 31;
    const int node0 = blockIdx.x * GBM;

    wmma::fragment<wmma::accumulator, 16, 16, 16, float> accm[8], accv[8];
#pragma unroll
    for (int c = 0; c < 8; c++) {
        wmma::fill_fragment(accm[c], 0.0f);
        wmma::fill_fragment(accv[c], 0.0f);
    }

    for (int k0 = 0; k0 < IN_F; k0 += GKC) {
        // --- feat tile: 128 rows x 32 k, fp32 -> fp16 ---
#pragma unroll
        for (int it = 0; it < 4; it++) {
            int idx = tid + 256 * it;        // 0..1023 float4 slots
            int row = idx >> 3;              // 8 float4 per row
            int kq  = idx & 7;
            int node = node0 + row;
            float4 a4 = make_float4(0.f, 0.f, 0.f, 0.f);
            if (node < n_nodes)
                a4 = *reinterpret_cast<const float4*>(&feat[(size_t)node * IN_F + k0 + kq * 4]);
            *reinterpret_cast<__half2*>(&As[row][kq * 4])     = __floats2half2_rn(a4.x, a4.y);
            *reinterpret_cast<__half2*>(&As[row][kq * 4 + 2]) = __floats2half2_rn(a4.z, a4.w);
        }
        // --- W tiles: 32 k x 128 cols x 2 matrices ---
#pragma unroll
        for (int it = 0; it < 4; it++) {
            int idx = tid + 256 * it;        // 0..1023
            int k  = idx >> 5;               // 32 float4 per row
            int c4 = idx & 31;
            float4 wm4 = *reinterpret_cast<const float4*>(&Wm[(size_t)(k0 + k) * OUT_F + c4 * 4]);
            float4 wv4 = *reinterpret_cast<const float4*>(&Wv[(size_t)(k0 + k) * OUT_F + c4 * 4]);
            *reinterpret_cast<__half2*>(&Wms[k][c4 * 4])     = __floats2half2_rn(wm4.x, wm4.y);
            *reinterpret_cast<__half2*>(&Wms[k][c4 * 4 + 2]) = __floats2half2_rn(wm4.z, wm4.w);
            *reinterpret_cast<__half2*>(&Wvs[k][c4 * 4])     = __floats2half2_rn(wv4.x, wv4.y);
            *reinterpret_cast<__half2*>(&Wvs[k][c4 * 4 + 2]) = __floats2half2_rn(wv4.z, wv4.w);
        }
        __syncthreads();

#pragma unroll
        for (int ks = 0; ks < GKC; ks += 16) {
            wmma::fragment<wmma::matrix_a, 16, 16, 16, __half, wmma::row_major> a;
            wmma::load_matrix_sync(a, &As[w * 16][ks], AS_LD);
#pragma unroll
            for (int c = 0; c < 8; c++) {
                wmma::fragment<wmma::matrix_b, 16, 16, 16, __half, wmma::row_major> b;
                wmma::load_matrix_sync(b, &Wms[ks][c * 16], WS_LD);
                wmma::mma_sync(accm[c], a, b, accm[c]);
                wmma::load_matrix_sync(b, &Wvs[ks][c * 16], WS_LD);
                wmma::mma_sync(accv[c], a, b, accv[c]);
            }
        }
        __syncthreads();
    }

    // --- epilogue: elementwise on fragment pairs (no row knowledge needed) ---
#pragma unroll
    for (int c = 0; c < 8; c++) {
#pragma unroll
        for (int i = 0; i < accm[c].num_elements; i++) {
            float mean = fmaxf(accm[c].x[i], 0.0f);
            float var  = fmaxf(accv[c].x[i], 0.0f);
            float att  = __expf(-var);       // GAMMA = 1
            accm[c].x[i] = mean * att;
            accv[c].x[i] = var * att * att;
        }
        // stage mean tile, write fp16
        wmma::store_matrix_sync(&stage[w][0], accm[c], 16, wmma::mem_row_major);
        __syncwarp();
#pragma unroll
        for (int t = lane; t < 128; t += 32) {   // 16 rows x 8 half2
            int r  = t >> 3;
            int c2 = t & 7;
            int node = node0 + w * 16 + r;
            if (node < n_nodes)
                *reinterpret_cast<__half2*>(&g_mh[(size_t)node * OUT_F + c * 16 + c2 * 2]) =
                    __floats2half2_rn(stage[w][r * 16 + c2 * 2], stage[w][r * 16 + c2 * 2 + 1]);
        }
        __syncwarp();
        // stage var tile, write fp16
        wmma::store_matrix_sync(&stage[w][0], accv[c], 16, wmma::mem_row_major);
        __syncwarp();
#pragma unroll
        for (int t = lane; t < 128; t += 32) {
            int r  = t >> 3;
            int c2 = t & 7;
            int node = node0 + w * 16 + r;
            if (node < n_nodes)
                *reinterpret_cast<__half2*>(&g_vh[(size_t)node * OUT_F + c * 16 + c2 * 2]) =
                    __floats2half2_rn(stage[w][r * 16 + c2 * 2], stage[w][r * 16 + c2 * 2 + 1]);
        }
        __syncwarp();
    }
}

// ---------------------------------------------------------------------
// Gather reduction: one block per dst node, 128 threads.
// tid 0-63: mean half2 cols (weight n1[src]); tid 64-127: var (weight n1^2).
__global__ __launch_bounds__(128)
void gather_kernel(float* __restrict__ out_mean,
                   float* __restrict__ out_var) {
    const int d = blockIdx.x;
    const int tid = threadIdx.x;
    const bool is_var = tid >= 64;
    const int c = tid & 63;

    const int start = g_rp[d];
    const int end   = g_rp[d + 1];

    __shared__ int   sh_src[128];
    __shared__ float sh_w[128];

    const __half2* base = is_var ? reinterpret_cast<const __half2*>(g_vh)
                                 : reinterpret_cast<const __half2*>(g_mh);
    float2 acc = make_float2(0.0f, 0.0f);

    for (int e0 = start; e0 < end; e0 += 128) {
        int cnt = min(128, end - e0);
        if (tid < cnt) {
            int s = g_csrc[e0 + tid];
            sh_src[tid] = s;
            sh_w[tid] = g_norm1[s];
        }
        __syncthreads();
        int i = 0;
        for (; i + 4 <= cnt; i += 4) {
            int s0 = sh_src[i],     s1 = sh_src[i + 1];
            int s2 = sh_src[i + 2], s3 = sh_src[i + 3];
            float w0 = sh_w[i],     w1 = sh_w[i + 1];
            float w2 = sh_w[i + 2], w3 = sh_w[i + 3];
            float2 f0 = __half22float2(base[(size_t)s0 * (OUT_F / 2) + c]);
            float2 f1 = __half22float2(base[(size_t)s1 * (OUT_F / 2) + c]);
            float2 f2 = __half22float2(base[(size_t)s2 * (OUT_F / 2) + c]);
            float2 f3 = __half22float2(base[(size_t)s3 * (OUT_F / 2) + c]);
            if (is_var) { w0 *= w0; w1 *= w1; w2 *= w2; w3 *= w3; }
            acc.x = fmaf(w0, f0.x, acc.x); acc.y = fmaf(w0, f0.y, acc.y);
            acc.x = fmaf(w1, f1.x, acc.x); acc.y = fmaf(w1, f1.y, acc.y);
            acc.x = fmaf(w2, f2.x, acc.x); acc.y = fmaf(w2, f2.y, acc.y);
            acc.x = fmaf(w3, f3.x, acc.x); acc.y = fmaf(w3, f3.y, acc.y);
        }
        for (; i < cnt; i++) {
            int s = sh_src[i];
            float w = sh_w[i];
            if (is_var) w *= w;
            float2 f = __half22float2(base[(size_t)s * (OUT_F / 2) + c]);
            acc.x = fmaf(w, f.x, acc.x);
            acc.y = fmaf(w, f.y, acc.y);
        }
        __syncthreads();
    }

    float n1 = g_norm1[d];
    float scale = is_var ? n1 * n1 : n1;
    float* outp = is_var ? out_var : out_mean;
    float2 res = make_float2(acc.x * scale, acc.y * scale);
    *reinterpret_cast<float2*>(&outp[(size_t)d * OUT_F + c * 2]) = res;
}

// ---------------------------------------------------------------------
extern "C" void kernel_launch(void* const* d_in, const int* in_sizes, int n_in,
                              void* d_out, int out_size) {
    const float* feat     = (const float*)d_in[0];
    const int*   edge_src = (const int*)  d_in[1];
    const int*   edge_dst = (const int*)  d_in[2];
    const float* Wm       = (const float*)d_in[3];
    const float* Wv       = (const float*)d_in[4];

    const int n_nodes = in_sizes[0] / IN_F;
    const int n_edges = in_sizes[1];

    float* out_mean = (float*)d_out;
    float* out_var  = out_mean + (size_t)n_nodes * OUT_F;

    int nb_scan = (n_nodes + SCAN_B - 1) / SCAN_B;

    // tensor-core GEMM (independent of CSR chain; longest pole first)
    gemm_tc_kernel<<<(n_nodes + GBM - 1) / GBM, 256>>>(feat, Wm, Wv, n_nodes);

    // CSR by dst + norms
    zero_cnt_kernel<<<(n_nodes + 255) / 256, 256>>>(n_nodes);
    count_kernel<<<(n_edges + 255) / 256, 256>>>(edge_dst, n_edges);
    scan1_kernel<<<nb_scan, SCAN_B>>>(n_nodes);
    scan2_kernel<<<1, 128>>>(nb_scan);
    scan3_kernel<<<nb_scan, SCAN_B>>>(n_nodes);
    fill_kernel<<<(n_edges + 255) / 256, 256>>>(edge_src, edge_dst, n_edges);

    // atomic-free gather reduction
    gather_kernel<<<n_nodes, 128>>>(out_mean, out_var);
}